// round 9
// baseline (speedup 1.0000x reference)
#include <cuda_runtime.h>
#include <cuda_fp16.h>
#include <cuda_bf16.h>

#define N_NODES 100000
#define DIM 128
#define E_MAX 640000
#define NBUCK 4096          // buckets used: ceil(100000/32) = 3125
#define BSHIFT 5            // bucket = src >> 5  (32-row window = 8 KB fp16)
#define EDGES_PER_BLOCK 512 // contiguous sorted edges per block (L1 locality)

// Normalized feature cache, fp16: 100000 rows * 256 B = 25.6 MB.
__device__ uint4 g_hn[(size_t)N_NODES * DIM * 2 / 16];
// Bucket sort scratch.
__device__ int g_cnt[NBUCK];
__device__ int g_cursor[NBUCK];
__device__ int g_ssrc[E_MAX];
__device__ int g_sdst[E_MAX];
__device__ int g_sidx[E_MAX];

// Kernel 1: one warp per row, normalize -> fp16 cache. Also zeroes counters.
__global__ void normalize_fp16_kernel(const float* __restrict__ h, int n) {
    int tid = blockIdx.x * blockDim.x + threadIdx.x;
    if (tid < NBUCK) g_cnt[tid] = 0;

    int row = tid >> 5;
    int lane = threadIdx.x & 31;
    if (row >= n) return;

    const float4 v = reinterpret_cast<const float4*>(h + (size_t)row * DIM)[lane];
    float s = v.x * v.x + v.y * v.y + v.z * v.z + v.w * v.w;
    #pragma unroll
    for (int off = 16; off > 0; off >>= 1)
        s += __shfl_xor_sync(0xFFFFFFFFu, s, off);

    float inv = 1.0f / fmaxf(sqrtf(s), 1e-12f);

    __half2 p0 = __floats2half2_rn(v.x * inv, v.y * inv);
    __half2 p1 = __floats2half2_rn(v.z * inv, v.w * inv);
    uint2 packed = make_uint2(*reinterpret_cast<unsigned*>(&p0),
                              *reinterpret_cast<unsigned*>(&p1));
    reinterpret_cast<uint2*>(g_hn)[(size_t)row * 32 + lane] = packed;
}

// Kernel 2: histogram of src buckets.
__global__ void hist_kernel(const int* __restrict__ src, int e, int n) {
    int i = blockIdx.x * blockDim.x + threadIdx.x;
    if (i >= e) return;
    int s = min(max(__ldg(src + i), 0), n - 1);
    atomicAdd(&g_cnt[s >> BSHIFT], 1);
}

// Kernel 3: single-block exclusive scan of NBUCK counters -> cursors.
__global__ void scan_kernel() {
    __shared__ int ssum[1024];
    int t = threadIdx.x;                 // 1024 threads, 4 counters each
    int base = t * 4;
    int c0 = g_cnt[base + 0], c1 = g_cnt[base + 1];
    int c2 = g_cnt[base + 2], c3 = g_cnt[base + 3];
    int s = c0 + c1 + c2 + c3;
    ssum[t] = s;
    __syncthreads();
    // Hillis-Steele inclusive scan over 1024 partial sums.
    for (int off = 1; off < 1024; off <<= 1) {
        int v = ssum[t];
        int add = (t >= off) ? ssum[t - off] : 0;
        __syncthreads();
        ssum[t] = v + add;
        __syncthreads();
    }
    int excl = ssum[t] - s;              // exclusive base for this thread's 4
    g_cursor[base + 0] = excl;           excl += c0;
    g_cursor[base + 1] = excl;           excl += c1;
    g_cursor[base + 2] = excl;           excl += c2;
    g_cursor[base + 3] = excl;
}

// Kernel 4: scatter edges into bucket order. Within-bucket order is
// nondeterministic (atomic), but output is scattered by orig id -> final
// result is order-invariant and deterministic.
__global__ void scatter_kernel(const int* __restrict__ src,
                               const int* __restrict__ dst, int e, int n) {
    int i = blockIdx.x * blockDim.x + threadIdx.x;
    if (i >= e) return;
    int s = min(max(__ldg(src + i), 0), n - 1);
    int d = min(max(__ldg(dst + i), 0), n - 1);
    int pos = atomicAdd(&g_cursor[s >> BSHIFT], 1);
    g_ssrc[pos] = s;
    g_sdst[pos] = d;
    g_sidx[pos] = i;
}

// Dot of 8 fp16 pairs in two uint4's, fp32 accumulation.
__device__ __forceinline__ float dot8h(uint4 a, uint4 b) {
    float acc = 0.0f;
    #pragma unroll
    for (int w = 0; w < 4; w++) {
        unsigned ua = (&a.x)[w], ub = (&b.x)[w];
        __half2 ha = *reinterpret_cast<__half2*>(&ua);
        __half2 hb = *reinterpret_cast<__half2*>(&ub);
        float2 fa = __half22float2(ha);
        float2 fb = __half22float2(hb);
        acc = fmaf(fa.x, fb.x, acc);
        acc = fmaf(fa.y, fb.y, acc);
    }
    return acc;
}

// Kernel 5: edge kernel over SORTED edges. 8 lanes/edge, 4 edges/warp per
// iteration, each warp owns 64 contiguous edges, block owns 512 contiguous
// edges -> per-block src window ~20 KB stays resident in L1.
__global__ void sddmm_cos_sorted_kernel(float* __restrict__ out, int e) {
    int lane = threadIdx.x & 31;
    int warp = threadIdx.x >> 5;         // 0..7
    int g = lane >> 3;                   // 0..3: edge within quad
    int l = lane & 7;                    // 0..7: lane within edge

    int warp_base = blockIdx.x * EDGES_PER_BLOCK + warp * 64;

    #pragma unroll 1
    for (int it = 0; it < 16; it++) {
        int e_idx = warp_base + it * 4 + g;
        bool valid = (e_idx < e);
        int ce = valid ? e_idx : (e - 1);

        int s_idx = __ldg(g_ssrc + ce);
        int d_idx = __ldg(g_sdst + ce);
        int o_idx = __ldg(g_sidx + ce);

        const uint4* a_row = g_hn + (size_t)s_idx * 16;
        const uint4* b_row = g_hn + (size_t)d_idx * 16;

        uint4 a0 = __ldg(a_row + l);
        uint4 a1 = __ldg(a_row + 8 + l);
        uint4 b0 = __ldg(b_row + l);
        uint4 b1 = __ldg(b_row + 8 + l);

        float acc = dot8h(a0, b0) + dot8h(a1, b1);

        #pragma unroll
        for (int off = 4; off > 0; off >>= 1)
            acc += __shfl_xor_sync(0xFFFFFFFFu, acc, off);

        if (l == 0 && valid)
            out[o_idx] = acc;
    }
}

extern "C" void kernel_launch(void* const* d_in, const int* in_sizes, int n_in,
                              void* d_out, int out_size) {
    const float* h   = (const float*)d_in[0];
    const int*   src = (const int*)d_in[1];   // int32 (JAX demotes int64)
    const int*   dst = (const int*)d_in[2];
    float* out = (float*)d_out;

    int n = in_sizes[0] / DIM;     // 100000
    int e = in_sizes[1];           // 640000

    {   // normalize + zero counters
        int blocks = (n * 32 + 255) / 256;
        normalize_fp16_kernel<<<blocks, 256>>>(h, n);
    }
    {   // histogram
        int blocks = (e + 255) / 256;
        hist_kernel<<<blocks, 256>>>(src, e, n);
    }
    scan_kernel<<<1, 1024>>>();
    {   // scatter
        int blocks = (e + 255) / 256;
        scatter_kernel<<<blocks, 256>>>(src, dst, e, n);
    }
    {   // edge kernel on sorted edges
        int blocks = (e + EDGES_PER_BLOCK - 1) / EDGES_PER_BLOCK;
        sddmm_cos_sorted_kernel<<<blocks, 256>>>(out, e);
    }
}

// round 12
// speedup vs baseline: 3.4971x; 3.4971x over previous
#include <cuda_runtime.h>
#include <cuda_fp16.h>
#include <cuda_bf16.h>

#define N_NODES 100000
#define DIM 128

// Normalized feature cache, fp16: 100000 rows * 256 B = 25.6 MB.
__device__ uint4 g_hn[(size_t)N_NODES * DIM * 2 / 16];

// Kernel 1: TWO rows per warp (MLP=2). Each lane loads float4 from both rows,
// two interleaved butterfly reductions, two packed fp16 stores.
__global__ void normalize_fp16_kernel(const float* __restrict__ h, int n) {
    int warp_id = (blockIdx.x * blockDim.x + threadIdx.x) >> 5;
    int lane = threadIdx.x & 31;
    int r0 = warp_id * 2;
    int r1 = r0 + 1;
    if (r0 >= n) return;
    bool has_r1 = (r1 < n);
    int r1c = has_r1 ? r1 : r0;

    const float4 v0 = __ldg(reinterpret_cast<const float4*>(h + (size_t)r0 * DIM) + lane);
    const float4 v1 = __ldg(reinterpret_cast<const float4*>(h + (size_t)r1c * DIM) + lane);

    float s0 = v0.x * v0.x + v0.y * v0.y + v0.z * v0.z + v0.w * v0.w;
    float s1 = v1.x * v1.x + v1.y * v1.y + v1.z * v1.z + v1.w * v1.w;
    #pragma unroll
    for (int off = 16; off > 0; off >>= 1) {
        s0 += __shfl_xor_sync(0xFFFFFFFFu, s0, off);
        s1 += __shfl_xor_sync(0xFFFFFFFFu, s1, off);
    }

    float inv0 = 1.0f / fmaxf(sqrtf(s0), 1e-12f);
    float inv1 = 1.0f / fmaxf(sqrtf(s1), 1e-12f);

    __half2 a0 = __floats2half2_rn(v0.x * inv0, v0.y * inv0);
    __half2 a1 = __floats2half2_rn(v0.z * inv0, v0.w * inv0);
    uint2 p0 = make_uint2(*reinterpret_cast<unsigned*>(&a0),
                          *reinterpret_cast<unsigned*>(&a1));
    reinterpret_cast<uint2*>(g_hn)[(size_t)r0 * 32 + lane] = p0;

    if (has_r1) {
        __half2 b0 = __floats2half2_rn(v1.x * inv1, v1.y * inv1);
        __half2 b1 = __floats2half2_rn(v1.z * inv1, v1.w * inv1);
        uint2 p1 = make_uint2(*reinterpret_cast<unsigned*>(&b0),
                              *reinterpret_cast<unsigned*>(&b1));
        reinterpret_cast<uint2*>(g_hn)[(size_t)r1 * 32 + lane] = p1;
    }
}

// Dot of 8 fp16 pairs in two uint4's, fp32 accumulation.
__device__ __forceinline__ float dot8h(uint4 a, uint4 b) {
    float acc = 0.0f;
    #pragma unroll
    for (int w = 0; w < 4; w++) {
        unsigned ua = (&a.x)[w], ub = (&b.x)[w];
        __half2 ha = *reinterpret_cast<__half2*>(&ua);
        __half2 hb = *reinterpret_cast<__half2*>(&ub);
        float2 fa = __half22float2(ha);
        float2 fb = __half22float2(hb);
        acc = fmaf(fa.x, fb.x, acc);
        acc = fmaf(fa.y, fb.y, acc);
    }
    return acc;
}

// Kernel 2: EIGHT edges per warp (two quads), 8 lanes/edge, 2 uint4/row/lane.
// All 8 row loads per thread are issued front-batched (MLP=8) before any FMA,
// then two independent dot+reduce chains. Every LDG.128 covers exactly one
// 128B line per 8-lane group.
__global__ void __launch_bounds__(256)
sddmm_cos_fp16_kernel(const int* __restrict__ src,
                      const int* __restrict__ dst,
                      float* __restrict__ out, int e, int n) {
    int warp_id = (blockIdx.x * blockDim.x + threadIdx.x) >> 5;
    int lane = threadIdx.x & 31;
    int g = lane >> 3;            // 0..3: edge within quad
    int l = lane & 7;             // 0..7: lane within edge

    int e0 = warp_id * 8 + g;     // quad 0
    int e1 = e0 + 4;              // quad 1
    if (e0 >= e) return;          // e % 8 == 0 -> whole warp exits together
    bool v1 = (e1 < e);
    int e1c = v1 ? e1 : e0;

    int s0 = min(max(__ldg(src + e0), 0), n - 1);
    int d0 = min(max(__ldg(dst + e0), 0), n - 1);
    int s1 = min(max(__ldg(src + e1c), 0), n - 1);
    int d1 = min(max(__ldg(dst + e1c), 0), n - 1);

    const uint4* sa0 = g_hn + (size_t)s0 * 16;
    const uint4* da0 = g_hn + (size_t)d0 * 16;
    const uint4* sa1 = g_hn + (size_t)s1 * 16;
    const uint4* da1 = g_hn + (size_t)d1 * 16;

    // Front-batched loads: 8 independent LDG.128 per thread.
    uint4 a0lo = __ldg(sa0 + l);
    uint4 a0hi = __ldg(sa0 + 8 + l);
    uint4 b0lo = __ldg(da0 + l);
    uint4 b0hi = __ldg(da0 + 8 + l);
    uint4 a1lo = __ldg(sa1 + l);
    uint4 a1hi = __ldg(sa1 + 8 + l);
    uint4 b1lo = __ldg(da1 + l);
    uint4 b1hi = __ldg(da1 + 8 + l);

    float acc0 = dot8h(a0lo, b0lo) + dot8h(a0hi, b0hi);
    float acc1 = dot8h(a1lo, b1lo) + dot8h(a1hi, b1hi);

    #pragma unroll
    for (int off = 4; off > 0; off >>= 1) {
        acc0 += __shfl_xor_sync(0xFFFFFFFFu, acc0, off);
        acc1 += __shfl_xor_sync(0xFFFFFFFFu, acc1, off);
    }

    if (l == 0) {
        out[e0] = acc0;
        if (v1) out[e1] = acc1;
    }
}

extern "C" void kernel_launch(void* const* d_in, const int* in_sizes, int n_in,
                              void* d_out, int out_size) {
    const float* h   = (const float*)d_in[0];
    const int*   src = (const int*)d_in[1];   // int32 (JAX demotes int64)
    const int*   dst = (const int*)d_in[2];
    float* out = (float*)d_out;

    int n = in_sizes[0] / DIM;     // 100000
    int e = in_sizes[1];           // 640000

    {   // Kernel 1: 2 rows/warp -> n/2 warps, 8 warps / 256-thread block
        int warps = (n + 1) / 2;
        int blocks = (warps + 7) / 8;
        normalize_fp16_kernel<<<blocks, 256>>>(h, n);
    }
    {   // Kernel 2: 8 edges/warp -> e/8 warps, 8 warps / block
        int warps = (e + 7) / 8;
        int blocks = (warps + 7) / 8;
        sddmm_cos_fp16_kernel<<<blocks, 256>>>(src, dst, out, e, n);
    }
}